// round 10
// baseline (speedup 1.0000x reference)
#include <cuda_runtime.h>
#include <cuda_fp16.h>
#include <math.h>
#include <stdint.h>

#define NB 32
#define NS 256
#define NH 768
#define KC 32
#define NCHUNK (NH / KC)   // 24
#define ROWB 80            // padded smem row stride: 64B data + 16B pad

// ---------------- device scratch ----------------
__device__ __half g_Qh[NB * NS * NH];
__device__ __half g_Kh[NB * NS * NH];
__device__ __half g_Kw[NB * NS * NH];     // decay-convolved K (scale included)
__device__ float g_Ksum[NB * NH];         // masked K column sums
__device__ float g_Mj[NB];                // valid-key counts
__device__ float g_w[NS];
__device__ float g_Sw[NB * NB * NS];      // q . Kw   per (i,j,s)
__device__ float g_Srow[NB * NB * NS];    // q . Ksum per (i,j,s)
__device__ float g_partial[NB * NB];

// ---------------- smem layout (2 buffers, A=256 rows, B=256 rows) ----------------
#define O_A   0                       // 256*80 = 20480
#define O_B   20480                   // 256*80 = 20480
#define BUF_SZ 40960
#define O_WS  (2 * BUF_SZ)            // 81920
#define O_KM  (O_WS + 1024)
#define O_QM  (O_KM + 1024)
#define O_RED (O_QM + 1024)
#define SMEM_NEED (O_RED + 64)

// ---------------- PTX helpers (base ISA only) ----------------
__device__ __forceinline__ uint32_t smem_u32(const void* p) {
    uint32_t a;
    asm("{ .reg .u64 t; cvta.to.shared.u64 t, %1; cvt.u32.u64 %0, t; }" : "=r"(a) : "l"(p));
    return a;
}
__device__ __forceinline__ void cpasync16(uint32_t s, const void* g) {
    asm volatile("cp.async.cg.shared.global [%0], [%1], 16;" :: "r"(s), "l"(g));
}
#define CP_COMMIT() asm volatile("cp.async.commit_group;" ::: "memory")
#define CP_WAIT0()  asm volatile("cp.async.wait_group 0;" ::: "memory")

__device__ __forceinline__ void ldsm4(uint32_t (&r)[4], uint32_t a) {
    asm volatile("ldmatrix.sync.aligned.m8n8.x4.shared.b16 {%0,%1,%2,%3}, [%4];"
                 : "=r"(r[0]), "=r"(r[1]), "=r"(r[2]), "=r"(r[3]) : "r"(a));
}
__device__ __forceinline__ void hmma(float* d, const uint32_t (&a)[4],
                                     uint32_t b0, uint32_t b1) {
    asm volatile(
        "mma.sync.aligned.m16n8k16.row.col.f32.f16.f16.f32 "
        "{%0,%1,%2,%3}, {%4,%5,%6,%7}, {%8,%9}, {%0,%1,%2,%3};"
        : "+f"(d[0]), "+f"(d[1]), "+f"(d[2]), "+f"(d[3])
        : "r"(a[0]), "r"(a[1]), "r"(a[2]), "r"(a[3]), "r"(b0), "r"(b1));
}

// ---------------------------------------------------------------------------
// Prep: one WARP per row, no block barriers. Block 0 also builds g_w.
// ---------------------------------------------------------------------------
__global__ void __launch_bounds__(256)
norm_all_kernel(const float* __restrict__ q, const float* __restrict__ k,
                const float* __restrict__ alpha_raw,
                const float* __restrict__ logit_scale) {
    int tid = threadIdx.x, wid = tid >> 5, lid = tid & 31;

    if (blockIdx.x == 0) {
        float a = alpha_raw[0];
        float alpha = (a > 20.f) ? a : log1pf(expf(a));
        float scale = expf(logit_scale[0]);
        g_w[tid] = scale * expf(-alpha * (float)tid);
    }

    int row = blockIdx.x * 8 + wid;          // 0..16383
    int which = row >= NB * NS;
    int r = which ? row - NB * NS : row;
    const float4* x = (const float4*)((which ? k : q) + (size_t)r * NH);

    float4 v[6];
    float ss = 0.f;
    #pragma unroll
    for (int t = 0; t < 6; ++t) {
        v[t] = x[lid + 32 * t];
        ss += v[t].x * v[t].x + v[t].y * v[t].y + v[t].z * v[t].z + v[t].w * v[t].w;
    }
    #pragma unroll
    for (int o = 16; o; o >>= 1) ss += __shfl_xor_sync(0xffffffffu, ss, o);
    float inv = 1.f / fmaxf(sqrtf(ss), 1e-12f);

    __half2* dst = (__half2*)((which ? g_Kh : g_Qh) + (size_t)r * NH);
    #pragma unroll
    for (int t = 0; t < 6; ++t) {
        int h2 = 2 * (lid + 32 * t);
        dst[h2]     = __floats2half2_rn(v[t].x * inv, v[t].y * inv);
        dst[h2 + 1] = __floats2half2_rn(v[t].z * inv, v[t].w * inv);
    }
}

// ---------------------------------------------------------------------------
// Conv: per (j,h): Kw[j,t,h] = scale * sum_u km_u k[j,u,h] r^|t-u|  (fwd+bwd pass)
// Also Ksum[j,h] and Mj[j]. grid 96 = 32 j x 3 h-blocks, 256 threads.
// ---------------------------------------------------------------------------
__global__ void __launch_bounds__(256)
conv_kernel(const float* __restrict__ kmask,
            const float* __restrict__ alpha_raw,
            const float* __restrict__ logit_scale) {
    int j = blockIdx.x / 3;
    int h = (blockIdx.x % 3) * 256 + threadIdx.x;
    __shared__ float kms[NS];
    kms[threadIdx.x] = (kmask[j * NS + threadIdx.x] > 0.f) ? 1.f : 0.f;
    __syncthreads();

    float a = alpha_raw[0];
    float alpha = (a > 20.f) ? a : log1pf(expf(a));
    float r = expf(-alpha);
    float scale = expf(logit_scale[0]);

    const __half* kp = g_Kh + (size_t)j * NS * NH + h;
    __half* kwp = g_Kw + (size_t)j * NS * NH + h;

    float ksum = 0.f, f = 0.f;
    for (int t = 0; t < NS; ++t) {
        float av = kms[t] * __half2float(kp[(size_t)t * NH]);
        ksum += av;
        f = av + r * f;                        // forward, incl self
        kwp[(size_t)t * NH] = __float2half(scale * f);
    }
    g_Ksum[j * NH + h] = ksum;

    float gIncl = 0.f;
    for (int t = NS - 1; t >= 0; --t) {
        float gAfter = r * gIncl;              // strictly-after sum
        float prev = __half2float(kwp[(size_t)t * NH]);
        kwp[(size_t)t * NH] = __float2half(prev + scale * gAfter);
        float av = kms[t] * __half2float(kp[(size_t)t * NH]);
        gIncl = av + gAfter;
    }

    if ((blockIdx.x % 3) == 0 && threadIdx.x == 0) {
        float m = 0.f;
        for (int t = 0; t < NS; ++t) m += kms[t];
        g_Mj[j] = m;
    }
}

// ---------------------------------------------------------------------------
// Swrow: per (s, j-block of 8): Sw[i,j,s] = q[i,s].Kw[j,s], Srow = q[i,s].Ksum[j]
// grid 1024 = 256 s x 4 jb; 256 threads -> (i = tid>>3, j = jb*8 + (tid&7)).
// ---------------------------------------------------------------------------
__global__ void __launch_bounds__(256)
swrow_kernel() {
    int s = blockIdx.x >> 2;
    int jb = blockIdx.x & 3;
    int tid = threadIdx.x;
    int i = tid >> 3;
    int j = jb * 8 + (tid & 7);

    const __half2* qrow = (const __half2*)(g_Qh + ((size_t)i * NS + s) * NH);
    const __half2* kwrow = (const __half2*)(g_Kw + ((size_t)j * NS + s) * NH);
    const float2* ksum = (const float2*)(g_Ksum + (size_t)j * NH);

    float sw = 0.f, srow = 0.f;
    #pragma unroll 4
    for (int t = 0; t < NH / 2; ++t) {
        float2 qv = __half22float2(qrow[t]);
        float2 wv = __half22float2(kwrow[t]);
        float2 kv = ksum[t];
        sw = fmaf(qv.x, wv.x, fmaf(qv.y, wv.y, sw));
        srow = fmaf(qv.x, kv.x, fmaf(qv.y, kv.y, srow));
    }
    size_t o = ((size_t)i * NB + j) * NS + s;
    g_Sw[o] = sw;
    g_Srow[o] = srow;
}

// ---------------------------------------------------------------------------
// Band kernel: blk = j*32 + i. CTA covers ALL 256 rows of pair (i,j).
// Warp w: rows [32w, 32w+32), exact sim on 64-col window clamp(32w-16,0,192).
// Far field handled linearly via Sw/Srow. No cross-warp softmax merge.
// ---------------------------------------------------------------------------
__device__ __forceinline__ void load_chunk(uint32_t sb, int buf, int c, int tid,
                                           const __half* Qp, const __half* Kp) {
    int k0 = c * KC;
    uint32_t bufb = sb + buf * BUF_SZ;
    #pragma unroll
    for (int it = 0; it < 4; ++it) {   // A: 256 rows x 4 groups (4/thread)
        int x = tid + it * 256;
        int r = x >> 2, g = x & 3;
        size_t go = (size_t)r * NH + k0 + g * 8;
        cpasync16(bufb + O_A + (uint32_t)(r * ROWB + g * 16), Qp + go);
    }
    #pragma unroll
    for (int it = 0; it < 4; ++it) {   // B: 256 rows x 4 groups (4/thread)
        int x = tid + it * 256;
        int r = x >> 2, g = x & 3;
        size_t go = (size_t)r * NH + k0 + g * 8;
        cpasync16(bufb + O_B + (uint32_t)(r * ROWB + g * 16), Kp + go);
    }
    CP_COMMIT();
}

__global__ void __launch_bounds__(256, 2)
li_band_kernel(const float* __restrict__ qmask, const float* __restrict__ kmask) {
    extern __shared__ char smem[];
    uint32_t sb = smem_u32(smem);

    int tid = threadIdx.x, wid = tid >> 5, lid = tid & 31;
    int blk = blockIdx.x;
    int j = blk >> 5;
    int i = blk & 31;

    float* ws = (float*)(smem + O_WS);
    float* km = (float*)(smem + O_KM);
    float* qm = (float*)(smem + O_QM);
    float* red = (float*)(smem + O_RED);
    ws[tid] = g_w[tid];
    km[tid] = kmask[j * NS + tid];
    qm[tid] = qmask[i * NS + tid];

    const __half* Qp = g_Qh + (size_t)i * NS * NH;
    const __half* Kp = g_Kh + (size_t)j * NS * NH;

    float acc[2][8][4];
    #pragma unroll
    for (int mf = 0; mf < 2; ++mf)
        #pragma unroll
        for (int nf = 0; nf < 8; ++nf)
            #pragma unroll
            for (int u = 0; u < 4; ++u) acc[mf][nf][u] = 0.f;

    // per-warp band window
    int m_base = wid * 32;
    int wb = m_base - 16;
    if (wb < 0) wb = 0;
    if (wb > 192) wb = 192;

    uint32_t a_off = (uint32_t)((m_base + (lid & 15)) * ROWB + ((lid >> 4) << 4));
    uint32_t b_row = ((lid >> 4) & 1) * 8 + (lid & 7);
    uint32_t b_off = (uint32_t)((wb + b_row) * ROWB + ((lid >> 3) & 1) * 16);

    load_chunk(sb, 0, 0, tid, Qp, Kp);

    for (int c = 0; c < NCHUNK; ++c) {
        CP_WAIT0();
        __syncthreads();
        if (c + 1 < NCHUNK)
            load_chunk(sb, (c + 1) & 1, c + 1, tid, Qp, Kp);

        uint32_t base = sb + (c & 1) * BUF_SZ;
        uint32_t A0[2][4], A1[2][4], Bf[2][4];
        ldsm4(A0[0], base + O_A + a_off);
        ldsm4(A1[0], base + O_A + a_off + 16 * ROWB);
        ldsm4(Bf[0], base + O_B + b_off);
        ldsm4(A0[1], base + O_A + a_off + 32);
        ldsm4(A1[1], base + O_A + a_off + 16 * ROWB + 32);
        #pragma unroll
        for (int t = 0; t < 8; ++t) {
            int ks = t >> 2, nb = t & 3;
            int cur = t & 1;
            if (t < 7) {
                int t1 = t + 1, ks1 = t1 >> 2, nb1 = t1 & 3;
                ldsm4(Bf[cur ^ 1], base + O_B + b_off + nb1 * 16 * ROWB + ks1 * 32);
            }
            hmma(acc[0][2 * nb],     A0[ks], Bf[cur][0], Bf[cur][1]);
            hmma(acc[0][2 * nb + 1], A0[ks], Bf[cur][2], Bf[cur][3]);
            hmma(acc[1][2 * nb],     A1[ks], Bf[cur][0], Bf[cur][1]);
            hmma(acc[1][2 * nb + 1], A1[ks], Bf[cur][2], Bf[cur][3]);
        }
    }
    __syncthreads();

    // ---- epilogue: per-warp rows, near-band exact + linear far field ----
    float shift = ws[0];
    float E = expf(-shift);
    float Mjv = g_Mj[j];
    const float* SwP = g_Sw + ((size_t)i * NB + j) * NS;
    const float* SrP = g_Srow + ((size_t)i * NB + j) * NS;

    int cb = 2 * (lid & 3);
    int rloc = lid >> 2;
    float warp_score = 0.f;
    #pragma unroll
    for (int mf = 0; mf < 2; ++mf) {
        #pragma unroll
        for (int half = 0; half < 2; ++half) {
            int s = m_base + mf * 16 + rloc + half * 8;
            float cse = 0.f, csec = 0.f;
            #pragma unroll
            for (int nf = 0; nf < 8; ++nf) {
                #pragma unroll
                for (int cc = 0; cc < 2; ++cc) {
                    int t = wb + nf * 8 + cb + cc;
                    if (km[t] > 0.f) {
                        float sim = acc[mf][nf][half * 2 + cc];
                        int d = s - t; d = d < 0 ? -d : d;
                        float l = sim * ws[d];
                        float e = __expf(l - shift);
                        cse += e - E * (1.f + l);
                        csec = fmaf(e - E, sim, csec);
                    }
                }
            }
            cse  += __shfl_xor_sync(0xffffffffu, cse, 1);
            cse  += __shfl_xor_sync(0xffffffffu, cse, 2);
            csec += __shfl_xor_sync(0xffffffffu, csec, 1);
            csec += __shfl_xor_sync(0xffffffffu, csec, 2);
            if ((lid & 3) == 0) {
                float qms = qm[s];
                float se = E * (Mjv + SwP[s]) + cse;
                float sec = E * SrP[s] + csec;
                if (se > 0.f && qms > 0.f) warp_score += (sec / se) * qms;
            }
        }
    }
    #pragma unroll
    for (int o = 16; o; o >>= 1)
        warp_score += __shfl_xor_sync(0xffffffffu, warp_score, o);
    if (lid == 0) red[wid] = warp_score;
    __syncthreads();
    if (tid == 0) {
        float tot = 0.f;
        #pragma unroll
        for (int w = 0; w < 8; ++w) tot += red[w];
        g_partial[blk] = tot;
    }
}

// ---------------------------------------------------------------------------
__global__ void reduce_kernel(const float* __restrict__ qmask, float* __restrict__ out) {
    int i = blockIdx.x;
    int tid = threadIdx.x;
    float v = qmask[i * NS + tid];
    #pragma unroll
    for (int o = 16; o; o >>= 1) v += __shfl_xor_sync(0xffffffffu, v, o);
    __shared__ float red[8];
    __shared__ float qsum_s;
    if ((tid & 31) == 0) red[tid >> 5] = v;
    __syncthreads();
    if (tid == 0) {
        float t = 0.f;
        #pragma unroll
        for (int w = 0; w < 8; ++w) t += red[w];
        qsum_s = fmaxf(t, 1.f);
    }
    __syncthreads();
    if (tid < NB) {
        int jj = tid;
        out[i * NB + jj] = g_partial[jj * NB + i] / qsum_s;
    }
}

extern "C" void kernel_launch(void* const* d_in, const int* in_sizes, int n_in,
                              void* d_out, int out_size) {
    const float* q           = (const float*)d_in[0];
    const float* k           = (const float*)d_in[1];
    const float* qmask       = (const float*)d_in[2];
    const float* kmask       = (const float*)d_in[3];
    const float* alpha_raw   = (const float*)d_in[4];
    const float* logit_scale = (const float*)d_in[5];
    float* out = (float*)d_out;

    cudaFuncSetAttribute(li_band_kernel, cudaFuncAttributeMaxDynamicSharedMemorySize, SMEM_NEED);

    norm_all_kernel<<<2 * NB * NS / 8, 256>>>(q, k, alpha_raw, logit_scale);
    conv_kernel<<<NB * 3, 256>>>(kmask, alpha_raw, logit_scale);
    swrow_kernel<<<NS * 4, 256>>>();
    li_band_kernel<<<NB * NB, 256, SMEM_NEED>>>(qmask, kmask);
    reduce_kernel<<<NB, 256>>>(qmask, out);
}

// round 11
// speedup vs baseline: 1.9455x; 1.9455x over previous
#include <cuda_runtime.h>
#include <cuda_fp16.h>
#include <math.h>
#include <stdint.h>

#define NB 32
#define NS 256
#define NH 768
#define KC 32
#define NCHUNK (NH / KC)   // 24
#define ROWB 80            // padded smem row stride: 64B data + 16B pad

// ---------------- device scratch ----------------
__device__ __half g_Qh[NB * NS * NH];
__device__ __half g_Kh[NB * NS * NH];
__device__ __half g_Kw[NB * NS * NH];     // decay-convolved K (scale included)
__device__ float g_Ksum[NB * NH];         // masked K column sums
__device__ float g_Mj[NB];                // valid-key counts
__device__ float g_w[NS];
__device__ float g_Sw[NB * NB * NS];      // q . Kw   per (i,j,s)
__device__ float g_Srow[NB * NB * NS];    // q . Ksum per (i,j,s)
__device__ float g_partial[NB * NB];

// ---------------- band-kernel smem layout ----------------
#define O_A   0                       // 256*80 = 20480
#define O_B   20480
#define BUF_SZ 40960
#define O_WS  (2 * BUF_SZ)            // 81920
#define O_KM  (O_WS + 1024)
#define O_QM  (O_KM + 1024)
#define O_RED (O_QM + 1024)
#define SMEM_NEED (O_RED + 64)

// ---------------- swrow smem layout ----------------
#define QS_STRIDE_U 385               // uint (=2 half) stride per row (768h + pad)
#define O_SQ   0                      // 32*385*4 = 49280
#define O_SW2  49280                  // Kws: 49280
#define O_SKS  98560                  // Ksum^T [768][33] float = 101376
#define SW_SMEM (98560 + 768 * 33 * 4)   // 199936

// ---------------- PTX helpers (base ISA only) ----------------
__device__ __forceinline__ uint32_t smem_u32(const void* p) {
    uint32_t a;
    asm("{ .reg .u64 t; cvta.to.shared.u64 t, %1; cvt.u32.u64 %0, t; }" : "=r"(a) : "l"(p));
    return a;
}
__device__ __forceinline__ void cpasync16(uint32_t s, const void* g) {
    asm volatile("cp.async.cg.shared.global [%0], [%1], 16;" :: "r"(s), "l"(g));
}
#define CP_COMMIT() asm volatile("cp.async.commit_group;" ::: "memory")
#define CP_WAIT0()  asm volatile("cp.async.wait_group 0;" ::: "memory")

__device__ __forceinline__ void ldsm4(uint32_t (&r)[4], uint32_t a) {
    asm volatile("ldmatrix.sync.aligned.m8n8.x4.shared.b16 {%0,%1,%2,%3}, [%4];"
                 : "=r"(r[0]), "=r"(r[1]), "=r"(r[2]), "=r"(r[3]) : "r"(a));
}
__device__ __forceinline__ void hmma(float* d, const uint32_t (&a)[4],
                                     uint32_t b0, uint32_t b1) {
    asm volatile(
        "mma.sync.aligned.m16n8k16.row.col.f32.f16.f16.f32 "
        "{%0,%1,%2,%3}, {%4,%5,%6,%7}, {%8,%9}, {%0,%1,%2,%3};"
        : "+f"(d[0]), "+f"(d[1]), "+f"(d[2]), "+f"(d[3])
        : "r"(a[0]), "r"(a[1]), "r"(a[2]), "r"(a[3]), "r"(b0), "r"(b1));
}

// ---------------------------------------------------------------------------
// Prep: one WARP per row. Block 0 also builds g_w.
// ---------------------------------------------------------------------------
__global__ void __launch_bounds__(256)
norm_all_kernel(const float* __restrict__ q, const float* __restrict__ k,
                const float* __restrict__ alpha_raw,
                const float* __restrict__ logit_scale) {
    int tid = threadIdx.x, wid = tid >> 5, lid = tid & 31;

    if (blockIdx.x == 0) {
        float a = alpha_raw[0];
        float alpha = (a > 20.f) ? a : log1pf(expf(a));
        float scale = expf(logit_scale[0]);
        g_w[tid] = scale * expf(-alpha * (float)tid);
    }

    int row = blockIdx.x * 8 + wid;
    int which = row >= NB * NS;
    int r = which ? row - NB * NS : row;
    const float4* x = (const float4*)((which ? k : q) + (size_t)r * NH);

    float4 v[6];
    float ss = 0.f;
    #pragma unroll
    for (int t = 0; t < 6; ++t) {
        v[t] = x[lid + 32 * t];
        ss += v[t].x * v[t].x + v[t].y * v[t].y + v[t].z * v[t].z + v[t].w * v[t].w;
    }
    #pragma unroll
    for (int o = 16; o; o >>= 1) ss += __shfl_xor_sync(0xffffffffu, ss, o);
    float inv = 1.f / fmaxf(sqrtf(ss), 1e-12f);

    __half2* dst = (__half2*)((which ? g_Kh : g_Qh) + (size_t)r * NH);
    #pragma unroll
    for (int t = 0; t < 6; ++t) {
        int h2 = 2 * (lid + 32 * t);
        dst[h2]     = __floats2half2_rn(v[t].x * inv, v[t].y * inv);
        dst[h2 + 1] = __floats2half2_rn(v[t].z * inv, v[t].w * inv);
    }
}

// ---------------------------------------------------------------------------
// Conv: Kw[j,t,h] = scale * sum_u km_u k[j,u,h] r^|t-u|; Ksum; Mj.
// ---------------------------------------------------------------------------
__global__ void __launch_bounds__(256)
conv_kernel(const float* __restrict__ kmask,
            const float* __restrict__ alpha_raw,
            const float* __restrict__ logit_scale) {
    int j = blockIdx.x / 3;
    int h = (blockIdx.x % 3) * 256 + threadIdx.x;
    __shared__ float kms[NS];
    kms[threadIdx.x] = (kmask[j * NS + threadIdx.x] > 0.f) ? 1.f : 0.f;
    __syncthreads();

    float a = alpha_raw[0];
    float alpha = (a > 20.f) ? a : log1pf(expf(a));
    float r = expf(-alpha);
    float scale = expf(logit_scale[0]);

    const __half* kp = g_Kh + (size_t)j * NS * NH + h;
    __half* kwp = g_Kw + (size_t)j * NS * NH + h;

    float ksum = 0.f, f = 0.f;
    for (int t = 0; t < NS; ++t) {
        float av = kms[t] * __half2float(kp[(size_t)t * NH]);
        ksum += av;
        f = av + r * f;
        kwp[(size_t)t * NH] = __float2half(scale * f);
    }
    g_Ksum[j * NH + h] = ksum;

    float gIncl = 0.f;
    for (int t = NS - 1; t >= 0; --t) {
        float gAfter = r * gIncl;
        float prev = __half2float(kwp[(size_t)t * NH]);
        kwp[(size_t)t * NH] = __float2half(prev + scale * gAfter);
        float av = kms[t] * __half2float(kp[(size_t)t * NH]);
        gIncl = av + gAfter;
    }

    if ((blockIdx.x % 3) == 0 && threadIdx.x == 0) {
        float m = 0.f;
        for (int t = 0; t < NS; ++t) m += kms[t];
        g_Mj[j] = m;
    }
}

// ---------------------------------------------------------------------------
// Swrow (REWRITTEN): one CTA per s. smem-tiled, 2i x 2j register tiles.
//   Sw[i,j,s]   = q[i,s] . Kw[j,s]
//   Srow[i,j,s] = q[i,s] . Ksum[j]
// ---------------------------------------------------------------------------
__global__ void __launch_bounds__(256, 1)
swrow_kernel() {
    extern __shared__ char sm[];
    int s = blockIdx.x;
    int tid = threadIdx.x;

    uint32_t* qs  = (uint32_t*)(sm + O_SQ);    // [32][385] uint (half2)
    uint32_t* kws = (uint32_t*)(sm + O_SW2);   // [32][385]
    float*    ksT = (float*)(sm + O_SKS);      // [768][33]

    // stage Q[:,s,:] and Kw[:,s,:] (coalesced)
    const uint32_t* qg = (const uint32_t*)g_Qh;
    const uint32_t* wg = (const uint32_t*)g_Kw;
    #pragma unroll
    for (int it = 0; it < 48; ++it) {          // 32*384 = 12288 / 256
        int idx = tid + it * 256;
        int r = idx / 384, c = idx - r * 384;
        size_t go = ((size_t)r * NS + s) * (NH / 2) + c;
        qs[r * QS_STRIDE_U + c]  = qg[go];
        kws[r * QS_STRIDE_U + c] = wg[go];
    }
    // stage Ksum transposed: read [j][h] coalesced, write [h][33]+j
    #pragma unroll
    for (int it = 0; it < 96; ++it) {          // 32*768 = 24576 / 256
        int idx = tid + it * 256;
        int r = idx / NH, h = idx - r * NH;
        ksT[h * 33 + r] = g_Ksum[idx];
    }
    __syncthreads();

    int ip = tid >> 4, jp = tid & 15;
    int i0 = 2 * ip, j0 = 2 * jp;
    const uint32_t* q0 = qs + i0 * QS_STRIDE_U;
    const uint32_t* q1 = q0 + QS_STRIDE_U;
    const uint32_t* w0 = kws + j0 * QS_STRIDE_U;
    const uint32_t* w1 = w0 + QS_STRIDE_U;

    float sw00 = 0.f, sw01 = 0.f, sw10 = 0.f, sw11 = 0.f;
    float sr00 = 0.f, sr01 = 0.f, sr10 = 0.f, sr11 = 0.f;
    #pragma unroll 4
    for (int h2 = 0; h2 < NH / 2; ++h2) {
        float2 a0 = __half22float2(*(const __half2*)&q0[h2]);
        float2 a1 = __half22float2(*(const __half2*)&q1[h2]);
        float2 b0 = __half22float2(*(const __half2*)&w0[h2]);
        float2 b1 = __half22float2(*(const __half2*)&w1[h2]);
        const float* ks = ksT + 66 * h2;       // row 2*h2
        float c0e = ks[j0],     c0o = ks[33 + j0];
        float c1e = ks[j0 + 1], c1o = ks[33 + j0 + 1];
        sw00 = fmaf(a0.x, b0.x, fmaf(a0.y, b0.y, sw00));
        sw01 = fmaf(a0.x, b1.x, fmaf(a0.y, b1.y, sw01));
        sw10 = fmaf(a1.x, b0.x, fmaf(a1.y, b0.y, sw10));
        sw11 = fmaf(a1.x, b1.x, fmaf(a1.y, b1.y, sw11));
        sr00 = fmaf(a0.x, c0e, fmaf(a0.y, c0o, sr00));
        sr01 = fmaf(a0.x, c1e, fmaf(a0.y, c1o, sr01));
        sr10 = fmaf(a1.x, c0e, fmaf(a1.y, c0o, sr10));
        sr11 = fmaf(a1.x, c1e, fmaf(a1.y, c1o, sr11));
    }

    size_t o00 = ((size_t)i0 * NB + j0) * NS + s;
    size_t o10 = o00 + (size_t)NB * NS;
    g_Sw[o00] = sw00;       g_Sw[o00 + NS] = sw01;
    g_Sw[o10] = sw10;       g_Sw[o10 + NS] = sw11;
    g_Srow[o00] = sr00;     g_Srow[o00 + NS] = sr01;
    g_Srow[o10] = sr10;     g_Srow[o10 + NS] = sr11;
}

// ---------------------------------------------------------------------------
// Band kernel (unchanged from Round 10): blk = j*32 + i, 256 rows per CTA.
// ---------------------------------------------------------------------------
__device__ __forceinline__ void load_chunk(uint32_t sb, int buf, int c, int tid,
                                           const __half* Qp, const __half* Kp) {
    int k0 = c * KC;
    uint32_t bufb = sb + buf * BUF_SZ;
    #pragma unroll
    for (int it = 0; it < 4; ++it) {
        int x = tid + it * 256;
        int r = x >> 2, g = x & 3;
        size_t go = (size_t)r * NH + k0 + g * 8;
        cpasync16(bufb + O_A + (uint32_t)(r * ROWB + g * 16), Qp + go);
    }
    #pragma unroll
    for (int it = 0; it < 4; ++it) {
        int x = tid + it * 256;
        int r = x >> 2, g = x & 3;
        size_t go = (size_t)r * NH + k0 + g * 8;
        cpasync16(bufb + O_B + (uint32_t)(r * ROWB + g * 16), Kp + go);
    }
    CP_COMMIT();
}

__global__ void __launch_bounds__(256, 2)
li_band_kernel(const float* __restrict__ qmask, const float* __restrict__ kmask) {
    extern __shared__ char smem[];
    uint32_t sb = smem_u32(smem);

    int tid = threadIdx.x, wid = tid >> 5, lid = tid & 31;
    int blk = blockIdx.x;
    int j = blk >> 5;
    int i = blk & 31;

    float* ws = (float*)(smem + O_WS);
    float* km = (float*)(smem + O_KM);
    float* qm = (float*)(smem + O_QM);
    float* red = (float*)(smem + O_RED);
    ws[tid] = g_w[tid];
    km[tid] = kmask[j * NS + tid];
    qm[tid] = qmask[i * NS + tid];

    const __half* Qp = g_Qh + (size_t)i * NS * NH;
    const __half* Kp = g_Kh + (size_t)j * NS * NH;

    float acc[2][8][4];
    #pragma unroll
    for (int mf = 0; mf < 2; ++mf)
        #pragma unroll
        for (int nf = 0; nf < 8; ++nf)
            #pragma unroll
            for (int u = 0; u < 4; ++u) acc[mf][nf][u] = 0.f;

    int m_base = wid * 32;
    int wb = m_base - 16;
    if (wb < 0) wb = 0;
    if (wb > 192) wb = 192;

    uint32_t a_off = (uint32_t)((m_base + (lid & 15)) * ROWB + ((lid >> 4) << 4));
    uint32_t b_row = ((lid >> 4) & 1) * 8 + (lid & 7);
    uint32_t b_off = (uint32_t)((wb + b_row) * ROWB + ((lid >> 3) & 1) * 16);

    load_chunk(sb, 0, 0, tid, Qp, Kp);

    for (int c = 0; c < NCHUNK; ++c) {
        CP_WAIT0();
        __syncthreads();
        if (c + 1 < NCHUNK)
            load_chunk(sb, (c + 1) & 1, c + 1, tid, Qp, Kp);

        uint32_t base = sb + (c & 1) * BUF_SZ;
        uint32_t A0[2][4], A1[2][4], Bf[2][4];
        ldsm4(A0[0], base + O_A + a_off);
        ldsm4(A1[0], base + O_A + a_off + 16 * ROWB);
        ldsm4(Bf[0], base + O_B + b_off);
        ldsm4(A0[1], base + O_A + a_off + 32);
        ldsm4(A1[1], base + O_A + a_off + 16 * ROWB + 32);
        #pragma unroll
        for (int t = 0; t < 8; ++t) {
            int ks = t >> 2, nb = t & 3;
            int cur = t & 1;
            if (t < 7) {
                int t1 = t + 1, ks1 = t1 >> 2, nb1 = t1 & 3;
                ldsm4(Bf[cur ^ 1], base + O_B + b_off + nb1 * 16 * ROWB + ks1 * 32);
            }
            hmma(acc[0][2 * nb],     A0[ks], Bf[cur][0], Bf[cur][1]);
            hmma(acc[0][2 * nb + 1], A0[ks], Bf[cur][2], Bf[cur][3]);
            hmma(acc[1][2 * nb],     A1[ks], Bf[cur][0], Bf[cur][1]);
            hmma(acc[1][2 * nb + 1], A1[ks], Bf[cur][2], Bf[cur][3]);
        }
    }
    __syncthreads();

    float shift = ws[0];
    float E = expf(-shift);
    float Mjv = g_Mj[j];
    const float* SwP = g_Sw + ((size_t)i * NB + j) * NS;
    const float* SrP = g_Srow + ((size_t)i * NB + j) * NS;

    int cb = 2 * (lid & 3);
    int rloc = lid >> 2;
    float warp_score = 0.f;
    #pragma unroll
    for (int mf = 0; mf < 2; ++mf) {
        #pragma unroll
        for (int half = 0; half < 2; ++half) {
            int s = m_base + mf * 16 + rloc + half * 8;
            float cse = 0.f, csec = 0.f;
            #pragma unroll
            for (int nf = 0; nf < 8; ++nf) {
                #pragma unroll
                for (int cc = 0; cc < 2; ++cc) {
                    int t = wb + nf * 8 + cb + cc;
                    if (km[t] > 0.f) {
                        float sim = acc[mf][nf][half * 2 + cc];
                        int d = s - t; d = d < 0 ? -d : d;
                        float l = sim * ws[d];
                        float e = __expf(l - shift);
                        cse += e - E * (1.f + l);
                        csec = fmaf(e - E, sim, csec);
                    }
                }
            }
            cse  += __shfl_xor_sync(0xffffffffu, cse, 1);
            cse  += __shfl_xor_sync(0xffffffffu, cse, 2);
            csec += __shfl_xor_sync(0xffffffffu, csec, 1);
            csec += __shfl_xor_sync(0xffffffffu, csec, 2);
            if ((lid & 3) == 0) {
                float qms = qm[s];
                float se = E * (Mjv + SwP[s]) + cse;
                float sec = E * SrP[s] + csec;
                if (se > 0.f && qms > 0.f) warp_score += (sec / se) * qms;
            }
        }
    }
    #pragma unroll
    for (int o = 16; o; o >>= 1)
        warp_score += __shfl_xor_sync(0xffffffffu, warp_score, o);
    if (lid == 0) red[wid] = warp_score;
    __syncthreads();
    if (tid == 0) {
        float tot = 0.f;
        #pragma unroll
        for (int w = 0; w < 8; ++w) tot += red[w];
        g_partial[blk] = tot;
    }
}

// ---------------------------------------------------------------------------
__global__ void reduce_kernel(const float* __restrict__ qmask, float* __restrict__ out) {
    int i = blockIdx.x;
    int tid = threadIdx.x;
    float v = qmask[i * NS + tid];
    #pragma unroll
    for (int o = 16; o; o >>= 1) v += __shfl_xor_sync(0xffffffffu, v, o);
    __shared__ float red[8];
    __shared__ float qsum_s;
    if ((tid & 31) == 0) red[tid >> 5] = v;
    __syncthreads();
    if (tid == 0) {
        float t = 0.f;
        #pragma unroll
        for (int w = 0; w < 8; ++w) t += red[w];
        qsum_s = fmaxf(t, 1.f);
    }
    __syncthreads();
    if (tid < NB) {
        int jj = tid;
        out[i * NB + jj] = g_partial[jj * NB + i] / qsum_s;
    }
}

extern "C" void kernel_launch(void* const* d_in, const int* in_sizes, int n_in,
                              void* d_out, int out_size) {
    const float* q           = (const float*)d_in[0];
    const float* k           = (const float*)d_in[1];
    const float* qmask       = (const float*)d_in[2];
    const float* kmask       = (const float*)d_in[3];
    const float* alpha_raw   = (const float*)d_in[4];
    const float* logit_scale = (const float*)d_in[5];
    float* out = (float*)d_out;

    cudaFuncSetAttribute(li_band_kernel, cudaFuncAttributeMaxDynamicSharedMemorySize, SMEM_NEED);
    cudaFuncSetAttribute(swrow_kernel, cudaFuncAttributeMaxDynamicSharedMemorySize, SW_SMEM);

    norm_all_kernel<<<2 * NB * NS / 8, 256>>>(q, k, alpha_raw, logit_scale);
    conv_kernel<<<NB * 3, 256>>>(kmask, alpha_raw, logit_scale);
    swrow_kernel<<<NS, 256, SW_SMEM>>>();
    li_band_kernel<<<NB * NB, 256, SMEM_NEED>>>(qmask, kmask);
    reduce_kernel<<<NB, 256>>>(qmask, out);
}

// round 13
// speedup vs baseline: 2.1664x; 1.1135x over previous
#include <cuda_runtime.h>
#include <cuda_fp16.h>
#include <math.h>
#include <stdint.h>

#define NB 32
#define NS 256
#define NH 768
#define KC 32
#define NCHUNK (NH / KC)   // 24
#define ROWB 80            // band-kernel smem row stride

// ---------------- device scratch ----------------
__device__ __half g_Qh[NB * NS * NH];
__device__ __half g_Kh[NB * NS * NH];
__device__ __half g_Kw[NB * NS * NH];     // decay-convolved K (scale included)
__device__ __half g_KsumH[NB * NH];       // masked K column sums (fp16)
__device__ float g_Mj[NB];                // valid-key counts
__device__ float g_w[NS];
__device__ float g_Sw[NB * NB * NS];      // q . Kw   per (i,j,s)
__device__ float g_Srow[NB * NB * NS];    // q . Ksum per (i,j,s)
__device__ float g_partial[NB * NB];

// ---------------- band-kernel smem layout ----------------
#define O_A   0                       // 256*80 = 20480
#define O_B   20480
#define BUF_SZ 40960
#define O_WS  (2 * BUF_SZ)            // 81920
#define O_KM  (O_WS + 1024)
#define O_QM  (O_KM + 1024)
#define O_RED (O_QM + 1024)
#define SMEM_NEED (O_RED + 64)

// ---------------- swrow-mma smem layout ----------------
#define AST   1552                    // 768*2 data + 16 pad (16B aligned)
#define SW_A  0                       // 32*1552 = 49664
#define SW_B  49664                   // 64*1552 = 99328
#define SW_RED (96 * AST)             // 148992: dedicated reduce buffer [8][2048] f32
#define SW_SMEM (SW_RED + 8 * 2048 * 4)   // 214528

// ---------------- PTX helpers (base ISA only) ----------------
__device__ __forceinline__ uint32_t smem_u32(const void* p) {
    uint32_t a;
    asm("{ .reg .u64 t; cvta.to.shared.u64 t, %1; cvt.u32.u64 %0, t; }" : "=r"(a) : "l"(p));
    return a;
}
__device__ __forceinline__ void cpasync16(uint32_t s, const void* g) {
    asm volatile("cp.async.cg.shared.global [%0], [%1], 16;" :: "r"(s), "l"(g));
}
#define CP_COMMIT() asm volatile("cp.async.commit_group;" ::: "memory")
#define CP_WAIT0()  asm volatile("cp.async.wait_group 0;" ::: "memory")

__device__ __forceinline__ void ldsm4(uint32_t (&r)[4], uint32_t a) {
    asm volatile("ldmatrix.sync.aligned.m8n8.x4.shared.b16 {%0,%1,%2,%3}, [%4];"
                 : "=r"(r[0]), "=r"(r[1]), "=r"(r[2]), "=r"(r[3]) : "r"(a));
}
__device__ __forceinline__ void hmma(float* d, const uint32_t (&a)[4],
                                     uint32_t b0, uint32_t b1) {
    asm volatile(
        "mma.sync.aligned.m16n8k16.row.col.f32.f16.f16.f32 "
        "{%0,%1,%2,%3}, {%4,%5,%6,%7}, {%8,%9}, {%0,%1,%2,%3};"
        : "+f"(d[0]), "+f"(d[1]), "+f"(d[2]), "+f"(d[3])
        : "r"(a[0]), "r"(a[1]), "r"(a[2]), "r"(a[3]), "r"(b0), "r"(b1));
}

// ---------------------------------------------------------------------------
// Prep: one WARP per row. Block 0 also builds g_w.
// ---------------------------------------------------------------------------
__global__ void __launch_bounds__(256)
norm_all_kernel(const float* __restrict__ q, const float* __restrict__ k,
                const float* __restrict__ alpha_raw,
                const float* __restrict__ logit_scale) {
    int tid = threadIdx.x, wid = tid >> 5, lid = tid & 31;

    if (blockIdx.x == 0) {
        float a = alpha_raw[0];
        float alpha = (a > 20.f) ? a : log1pf(expf(a));
        float scale = expf(logit_scale[0]);
        g_w[tid] = scale * expf(-alpha * (float)tid);
    }

    int row = blockIdx.x * 8 + wid;
    int which = row >= NB * NS;
    int r = which ? row - NB * NS : row;
    const float4* x = (const float4*)((which ? k : q) + (size_t)r * NH);

    float4 v[6];
    float ss = 0.f;
    #pragma unroll
    for (int t = 0; t < 6; ++t) {
        v[t] = x[lid + 32 * t];
        ss += v[t].x * v[t].x + v[t].y * v[t].y + v[t].z * v[t].z + v[t].w * v[t].w;
    }
    #pragma unroll
    for (int o = 16; o; o >>= 1) ss += __shfl_xor_sync(0xffffffffu, ss, o);
    float inv = 1.f / fmaxf(sqrtf(ss), 1e-12f);

    __half2* dst = (__half2*)((which ? g_Kh : g_Qh) + (size_t)r * NH);
    #pragma unroll
    for (int t = 0; t < 6; ++t) {
        int h2 = 2 * (lid + 32 * t);
        dst[h2]     = __floats2half2_rn(v[t].x * inv, v[t].y * inv);
        dst[h2 + 1] = __floats2half2_rn(v[t].z * inv, v[t].w * inv);
    }
}

// ---------------------------------------------------------------------------
// Conv: Kw[j,t,h] = scale * sum_u km_u k[j,u,h] r^|t-u|; KsumH (fp16); Mj.
// ---------------------------------------------------------------------------
__global__ void __launch_bounds__(256)
conv_kernel(const float* __restrict__ kmask,
            const float* __restrict__ alpha_raw,
            const float* __restrict__ logit_scale) {
    int j = blockIdx.x / 3;
    int h = (blockIdx.x % 3) * 256 + threadIdx.x;
    __shared__ float kms[NS];
    kms[threadIdx.x] = (kmask[j * NS + threadIdx.x] > 0.f) ? 1.f : 0.f;
    __syncthreads();

    float a = alpha_raw[0];
    float alpha = (a > 20.f) ? a : log1pf(expf(a));
    float r = expf(-alpha);
    float scale = expf(logit_scale[0]);

    const __half* kp = g_Kh + (size_t)j * NS * NH + h;
    __half* kwp = g_Kw + (size_t)j * NS * NH + h;

    float ksum = 0.f, f = 0.f;
    for (int t = 0; t < NS; ++t) {
        float av = kms[t] * __half2float(kp[(size_t)t * NH]);
        ksum += av;
        f = av + r * f;
        kwp[(size_t)t * NH] = __float2half(scale * f);
    }
    g_KsumH[j * NH + h] = __float2half(ksum);

    float gIncl = 0.f;
    for (int t = NS - 1; t >= 0; --t) {
        float gAfter = r * gIncl;
        float prev = __half2float(kwp[(size_t)t * NH]);
        kwp[(size_t)t * NH] = __float2half(prev + scale * gAfter);
        float av = kms[t] * __half2float(kp[(size_t)t * NH]);
        gIncl = av + gAfter;
    }

    if ((blockIdx.x % 3) == 0 && threadIdx.x == 0) {
        float m = 0.f;
        for (int t = 0; t < NS; ++t) m += kms[t];
        g_Mj[j] = m;
    }
}

// ---------------------------------------------------------------------------
// Swrow (TENSOR-CORE): one CTA per s. 32x64x768 GEMM:
//   A = Q[:, s, :] (32 x 768),  B rows 0-31 = Kw[:, s, :], rows 32-63 = KsumH.
//   out[i][j]    = Sw[i,j,s];   out[i][32+j] = Srow[i,j,s].
// 8 warps split K (96 elems each), dedicated fp32 smem reduce.
// NOTE: each 768-half row = 96 16-byte groups (bug in R12 staged only 48).
// ---------------------------------------------------------------------------
__global__ void __launch_bounds__(256, 1)
swrow_kernel() {
    extern __shared__ char sm[];
    uint32_t sb = smem_u32(sm);
    int s = blockIdx.x;
    int tid = threadIdx.x, wid = tid >> 5, lid = tid & 31;

    // stage A (32 rows x 96 16B-groups = 3072)
    #pragma unroll
    for (int it = 0; it < 12; ++it) {
        int idx = tid + it * 256;
        int r = idx / 96, g = idx - r * 96;
        cpasync16(sb + SW_A + (uint32_t)(r * AST + g * 16),
                  g_Qh + ((size_t)r * NS + s) * NH + g * 8);
    }
    // stage B (64 rows x 96 groups = 6144)
    #pragma unroll
    for (int it = 0; it < 24; ++it) {
        int idx = tid + it * 256;
        int r = idx / 96, g = idx - r * 96;
        const __half* src = (r < 32)
            ? g_Kw + ((size_t)r * NS + s) * NH + g * 8
            : g_KsumH + (size_t)(r - 32) * NH + g * 8;
        cpasync16(sb + SW_B + (uint32_t)(r * AST + g * 16), src);
    }
    CP_COMMIT();
    CP_WAIT0();
    __syncthreads();

    float acc[2][8][4];
    #pragma unroll
    for (int mf = 0; mf < 2; ++mf)
        #pragma unroll
        for (int nf = 0; nf < 8; ++nf)
            #pragma unroll
            for (int u = 0; u < 4; ++u) acc[mf][nf][u] = 0.f;

    uint32_t a_base = sb + SW_A + (lid & 15) * AST + ((lid >> 4) << 4);
    uint32_t b_base = sb + SW_B + (((lid >> 4) & 1) * 8 + (lid & 7)) * AST
                      + (((lid >> 3) & 1) << 4);

    #pragma unroll
    for (int step = 0; step < 6; ++step) {
        uint32_t kb = (uint32_t)(wid * 6 + step) * 32;   // 48 k16-steps * 32B
        uint32_t A0[4], A1[4];
        ldsm4(A0, a_base + kb);
        ldsm4(A1, a_base + 16 * AST + kb);
        #pragma unroll
        for (int nb = 0; nb < 4; ++nb) {
            uint32_t B[4];
            ldsm4(B, b_base + nb * 16 * AST + kb);
            hmma(acc[0][2 * nb],     A0, B[0], B[1]);
            hmma(acc[0][2 * nb + 1], A0, B[2], B[3]);
            hmma(acc[1][2 * nb],     A1, B[0], B[1]);
            hmma(acc[1][2 * nb + 1], A1, B[2], B[3]);
        }
    }
    __syncthreads();

    // dedicated reduce buffer (no aliasing with staged data)
    float* red = (float*)(sm + SW_RED);     // [8][2048]
    float* mine = red + wid * 2048;
    #pragma unroll
    for (int mf = 0; mf < 2; ++mf)
        #pragma unroll
        for (int nf = 0; nf < 8; ++nf)
            #pragma unroll
            for (int u = 0; u < 4; ++u) {
                int row = mf * 16 + (lid >> 2) + ((u >> 1) << 3);
                int col = nf * 8 + 2 * (lid & 3) + (u & 1);
                mine[row * 64 + col] = acc[mf][nf][u];
            }
    __syncthreads();

    #pragma unroll
    for (int it = 0; it < 8; ++it) {
        int idx = tid + it * 256;      // 0..2047
        float v = 0.f;
        #pragma unroll
        for (int w = 0; w < 8; ++w) v += red[w * 2048 + idx];
        int row = idx >> 6, col = idx & 63;
        if (col < 32) g_Sw[((size_t)row * NB + col) * NS + s] = v;
        else          g_Srow[((size_t)row * NB + (col - 32)) * NS + s] = v;
    }
}

// ---------------------------------------------------------------------------
// Band kernel: blk = j*32 + i. 48-wide exact windows per 16-row group
// (union 64-row B tile per warp; guarded HMMA, lo in {0,1} frag offset).
// ---------------------------------------------------------------------------
__device__ __forceinline__ void load_chunk(uint32_t sb, int buf, int c, int tid,
                                           const __half* Qp, const __half* Kp) {
    int k0 = c * KC;
    uint32_t bufb = sb + buf * BUF_SZ;
    #pragma unroll
    for (int it = 0; it < 4; ++it) {
        int x = tid + it * 256;
        int r = x >> 2, g = x & 3;
        size_t go = (size_t)r * NH + k0 + g * 8;
        cpasync16(bufb + O_A + (uint32_t)(r * ROWB + g * 16), Qp + go);
    }
    #pragma unroll
    for (int it = 0; it < 4; ++it) {
        int x = tid + it * 256;
        int r = x >> 2, g = x & 3;
        size_t go = (size_t)r * NH + k0 + g * 8;
        cpasync16(bufb + O_B + (uint32_t)(r * ROWB + g * 16), Kp + go);
    }
    CP_COMMIT();
}

__global__ void __launch_bounds__(256, 2)
li_band_kernel(const float* __restrict__ qmask, const float* __restrict__ kmask) {
    extern __shared__ char smem[];
    uint32_t sb = smem_u32(smem);

    int tid = threadIdx.x, wid = tid >> 5, lid = tid & 31;
    int blk = blockIdx.x;
    int j = blk >> 5;
    int i = blk & 31;

    float* ws = (float*)(smem + O_WS);
    float* km = (float*)(smem + O_KM);
    float* qm = (float*)(smem + O_QM);
    float* red = (float*)(smem + O_RED);
    ws[tid] = g_w[tid];
    km[tid] = kmask[j * NS + tid];
    qm[tid] = qmask[i * NS + tid];

    const __half* Qp = g_Qh + (size_t)i * NS * NH;
    const __half* Kp = g_Kh + (size_t)j * NS * NH;

    float acc[2][8][4];
    #pragma unroll
    for (int mf = 0; mf < 2; ++mf)
        #pragma unroll
        for (int nf = 0; nf < 8; ++nf)
            #pragma unroll
            for (int u = 0; u < 4; ++u) acc[mf][nf][u] = 0.f;

    int m_base = wid * 32;
    int wb = m_base - 16;
    if (wb < 0) wb = 0;
    if (wb > 192) wb = 192;
    // 48-wide windows: mf0 uses B-ldsm nb in [lo0, lo0+2], mf1 nb in [lo1, lo1+2]
    int lo0 = (wid == 7) ? 1 : 0;
    int lo1 = (wid == 0) ? 0 : 1;

    uint32_t a_off = (uint32_t)((m_base + (lid & 15)) * ROWB + ((lid >> 4) << 4));
    uint32_t b_row = ((lid >> 4) & 1) * 8 + (lid & 7);
    uint32_t b_off = (uint32_t)((wb + b_row) * ROWB + ((lid >> 3) & 1) * 16);

    load_chunk(sb, 0, 0, tid, Qp, Kp);

    for (int c = 0; c < NCHUNK; ++c) {
        CP_WAIT0();
        __syncthreads();
        if (c + 1 < NCHUNK)
            load_chunk(sb, (c + 1) & 1, c + 1, tid, Qp, Kp);

        uint32_t base = sb + (c & 1) * BUF_SZ;
        uint32_t A0[2][4], A1[2][4], Bf[2][4];
        ldsm4(A0[0], base + O_A + a_off);
        ldsm4(A1[0], base + O_A + a_off + 16 * ROWB);
        ldsm4(Bf[0], base + O_B + b_off);
        ldsm4(A0[1], base + O_A + a_off + 32);
        ldsm4(A1[1], base + O_A + a_off + 16 * ROWB + 32);
        #pragma unroll
        for (int t = 0; t < 8; ++t) {
            int ks = t >> 2, nb = t & 3;
            int cur = t & 1;
            if (t < 7) {
                int t1 = t + 1, ks1 = t1 >> 2, nb1 = t1 & 3;
                ldsm4(Bf[cur ^ 1], base + O_B + b_off + nb1 * 16 * ROWB + ks1 * 32);
            }
            if (nb >= lo0 && nb <= lo0 + 2) {
                hmma(acc[0][2 * nb],     A0[ks], Bf[cur][0], Bf[cur][1]);
                hmma(acc[0][2 * nb + 1], A0[ks], Bf[cur][2], Bf[cur][3]);
            }
            if (nb >= lo1 && nb <= lo1 + 2) {
                hmma(acc[1][2 * nb],     A1[ks], Bf[cur][0], Bf[cur][1]);
                hmma(acc[1][2 * nb + 1], A1[ks], Bf[cur][2], Bf[cur][3]);
            }
        }
    }
    __syncthreads();

    float shift = ws[0];
    float E = expf(-shift);
    float Mjv = g_Mj[j];
    const float* SwP = g_Sw + ((size_t)i * NB + j) * NS;
    const float* SrP = g_Srow + ((size_t)i * NB + j) * NS;

    int cb = 2 * (lid & 3);
    int rloc = lid >> 2;
    float warp_score = 0.f;
    #pragma unroll
    for (int mf = 0; mf < 2; ++mf) {
        int lo = mf ? lo1 : lo0;
        #pragma unroll
        for (int half = 0; half < 2; ++half) {
            int s = m_base + mf * 16 + rloc + half * 8;
            float cse = 0.f, csec = 0.f;
            #pragma unroll
            for (int nf = 0; nf < 8; ++nf) {
                if (nf >= 2 * lo && nf < 2 * lo + 6) {
                    #pragma unroll
                    for (int cc = 0; cc < 2; ++cc) {
                        int t = wb + nf * 8 + cb + cc;
                        if (km[t] > 0.f) {
                            float sim = acc[mf][nf][half * 2 + cc];
                            int d = s - t; d = d < 0 ? -d : d;
                            float l = sim * ws[d];
                            float e = __expf(l - shift);
                            cse += e - E * (1.f + l);
                            csec = fmaf(e - E, sim, csec);
                        }
                    }
                }
            }
            cse  += __shfl_xor_sync(0xffffffffu, cse, 1);
            cse  += __shfl_xor_sync(0xffffffffu, cse, 2);
            csec += __shfl_xor_sync(0xffffffffu, csec, 1);
            csec += __shfl_xor_sync(0xffffffffu, csec, 2);
            if ((lid & 3) == 0) {
                float qms = qm[s];
                float se = E * (Mjv + SwP[s]) + cse;
                float sec = E * SrP[s] + csec;
                if (se > 0.f && qms > 0.f) warp_score += (sec / se) * qms;
            }
        }
    }
    #pragma unroll
    for (int o = 16; o; o >>= 1)
        warp_score += __shfl_xor_sync(0xffffffffu, warp_score, o);
    if (lid == 0) red[wid] = warp_score;
    __syncthreads();
    if (tid == 0) {
        float tot = 0.f;
        #pragma unroll
        for (int w = 0; w < 8; ++w) tot += red[w];
        g_partial[blk] = tot;
    }
}

// ---------------------------------------------------------------------------
__global__ void reduce_kernel(const float* __restrict__ qmask, float* __restrict__ out) {
    int i = blockIdx.x;
    int tid = threadIdx.x;
    float v = qmask[i * NS + tid];
    #pragma unroll
    for (int o = 16; o; o >>= 1) v += __shfl_xor_sync(0xffffffffu, v, o);
    __shared__ float red[8];
    __shared__ float qsum_s;
    if ((tid & 31) == 0) red[tid >> 5] = v;
    __syncthreads();
    if (tid == 0) {
        float t = 0.f;
        #pragma unroll
        for (int w = 0; w < 8; ++w) t += red[w];
        qsum_s = fmaxf(t, 1.f);
    }
    __syncthreads();
    if (tid < NB) {
        int jj = tid;
        out[i * NB + jj] = g_partial[jj * NB + i] / qsum_s;
    }
}

extern "C" void kernel_launch(void* const* d_in, const int* in_sizes, int n_in,
                              void* d_out, int out_size) {
    const float* q           = (const float*)d_in[0];
    const float* k           = (const float*)d_in[1];
    const float* qmask       = (const float*)d_in[2];
    const float* kmask       = (const float*)d_in[3];
    const float* alpha_raw   = (const float*)d_in[4];
    const float* logit_scale = (const float*)d_in[5];
    float* out = (float*)d_out;

    cudaFuncSetAttribute(li_band_kernel, cudaFuncAttributeMaxDynamicSharedMemorySize, SMEM_NEED);
    cudaFuncSetAttribute(swrow_kernel, cudaFuncAttributeMaxDynamicSharedMemorySize, SW_SMEM);

    norm_all_kernel<<<2 * NB * NS / 8, 256>>>(q, k, alpha_raw, logit_scale);
    conv_kernel<<<NB * 3, 256>>>(kmask, alpha_raw, logit_scale);
    swrow_kernel<<<NS, 256, SW_SMEM>>>();
    li_band_kernel<<<NB * NB, 256, SMEM_NEED>>>(qmask, kmask);
    reduce_kernel<<<NB, 256>>>(qmask, out);
}

// round 14
// speedup vs baseline: 2.5718x; 1.1871x over previous
#include <cuda_runtime.h>
#include <cuda_fp16.h>
#include <math.h>
#include <stdint.h>

#define NB 32
#define NS 256
#define NH 768
#define KC 64
#define NCHUNK (NH / KC)   // 12
#define ROWB 144           // 128B data + 16 pad, conflict-free (stride 36 banks)

// ---------------- device scratch ----------------
__device__ __half g_Qh[NB * NS * NH];
__device__ __half g_Kh[NB * NS * NH];
__device__ __half g_Kw[NB * NS * NH];     // decay-convolved K (scale included)
__device__ __half g_KsumH[NB * NH];       // masked K column sums (fp16)
__device__ float g_Mj[NB];                // valid-key counts
__device__ float g_w[NS];
__device__ float g_Sw[NB * NB * NS];      // q . Kw   per (i,j,s)
__device__ float g_Srow[NB * NB * NS];    // q . Ksum per (i,j,s)
__device__ float g_partial[NB * NB];

// ---------------- band-v2 smem layout (2 j per CTA, KC=64, 2 buffers) --------
#define A_SZ  (256 * ROWB)            // 36864
#define BJ    (256 * ROWB)            // 36864 per j
#define O_BB  A_SZ                    // B base within buffer
#define BUF_SZ (A_SZ + 2 * BJ)        // 110592
#define O_WS  (2 * BUF_SZ)            // 221184
#define O_KM  (O_WS + 1024)           // 2048 (two j)
#define O_QM  (O_KM + 2048)
#define O_RED (O_QM + 1024)           // [2][8]
#define SMEM_NEED (O_RED + 128)       // 225408

// ---------------- swrow smem layout ----------------
#define AST   1552
#define SW_A  0
#define SW_B  49664
#define SW_RED (96 * AST)             // 148992
#define SW_SMEM (SW_RED + 8 * 2048 * 4)   // 214528

// ---------------- conv smem ----------------
#define CONV_SMEM (131072 + 1024)     // fbuf[256][256] half + kms[256]

// ---------------- PTX helpers (base ISA only) ----------------
__device__ __forceinline__ uint32_t smem_u32(const void* p) {
    uint32_t a;
    asm("{ .reg .u64 t; cvta.to.shared.u64 t, %1; cvt.u32.u64 %0, t; }" : "=r"(a) : "l"(p));
    return a;
}
__device__ __forceinline__ void cpasync16(uint32_t s, const void* g) {
    asm volatile("cp.async.cg.shared.global [%0], [%1], 16;" :: "r"(s), "l"(g));
}
#define CP_COMMIT() asm volatile("cp.async.commit_group;" ::: "memory")
#define CP_WAIT0()  asm volatile("cp.async.wait_group 0;" ::: "memory")

__device__ __forceinline__ void ldsm4(uint32_t (&r)[4], uint32_t a) {
    asm volatile("ldmatrix.sync.aligned.m8n8.x4.shared.b16 {%0,%1,%2,%3}, [%4];"
                 : "=r"(r[0]), "=r"(r[1]), "=r"(r[2]), "=r"(r[3]) : "r"(a));
}
__device__ __forceinline__ void hmma(float* d, const uint32_t (&a)[4],
                                     uint32_t b0, uint32_t b1) {
    asm volatile(
        "mma.sync.aligned.m16n8k16.row.col.f32.f16.f16.f32 "
        "{%0,%1,%2,%3}, {%4,%5,%6,%7}, {%8,%9}, {%0,%1,%2,%3};"
        : "+f"(d[0]), "+f"(d[1]), "+f"(d[2]), "+f"(d[3])
        : "r"(a[0]), "r"(a[1]), "r"(a[2]), "r"(a[3]), "r"(b0), "r"(b1));
}

// ---------------------------------------------------------------------------
// Prep: one WARP per row. Block 0 also builds g_w.
// ---------------------------------------------------------------------------
__global__ void __launch_bounds__(256)
norm_all_kernel(const float* __restrict__ q, const float* __restrict__ k,
                const float* __restrict__ alpha_raw,
                const float* __restrict__ logit_scale) {
    int tid = threadIdx.x, wid = tid >> 5, lid = tid & 31;

    if (blockIdx.x == 0) {
        float a = alpha_raw[0];
        float alpha = (a > 20.f) ? a : log1pf(expf(a));
        float scale = expf(logit_scale[0]);
        g_w[tid] = scale * expf(-alpha * (float)tid);
    }

    int row = blockIdx.x * 8 + wid;
    int which = row >= NB * NS;
    int r = which ? row - NB * NS : row;
    const float4* x = (const float4*)((which ? k : q) + (size_t)r * NH);

    float4 v[6];
    float ss = 0.f;
    #pragma unroll
    for (int t = 0; t < 6; ++t) {
        v[t] = x[lid + 32 * t];
        ss += v[t].x * v[t].x + v[t].y * v[t].y + v[t].z * v[t].z + v[t].w * v[t].w;
    }
    #pragma unroll
    for (int o = 16; o; o >>= 1) ss += __shfl_xor_sync(0xffffffffu, ss, o);
    float inv = 1.f / fmaxf(sqrtf(ss), 1e-12f);

    __half2* dst = (__half2*)((which ? g_Kh : g_Qh) + (size_t)r * NH);
    #pragma unroll
    for (int t = 0; t < 6; ++t) {
        int h2 = 2 * (lid + 32 * t);
        dst[h2]     = __floats2half2_rn(v[t].x * inv, v[t].y * inv);
        dst[h2 + 1] = __floats2half2_rn(v[t].z * inv, v[t].w * inv);
    }
}

// ---------------------------------------------------------------------------
// Conv v2: batched (MLP-16) loads + smem forward-intermediate.
// Same math/rounding as v1: Kw[t] = scale*f_t(fwd incl) + scale*g_t(bwd excl).
// grid 96 = j x 3 h-blocks, 256 threads (one h each).
// ---------------------------------------------------------------------------
#define CONV_LOAD(ARR, T0)                                                    \
    _Pragma("unroll")                                                         \
    for (int u = 0; u < 16; ++u)                                              \
        ARR[u] = kms[(T0) + u] * __half2float(kp[(size_t)((T0) + u) * NH]);

#define CONV_LOADR(ARR, T0)                                                   \
    _Pragma("unroll")                                                         \
    for (int u = 0; u < 16; ++u)                                              \
        ARR[u] = kms[(T0) - u] * __half2float(kp[(size_t)((T0) - u) * NH]);

__global__ void __launch_bounds__(256, 1)
conv_kernel(const float* __restrict__ kmask,
            const float* __restrict__ alpha_raw,
            const float* __restrict__ logit_scale) {
    extern __shared__ char sm[];
    __half* fbuf = (__half*)sm;                // [256 t][256 h]
    float* kms = (float*)(sm + 131072);
    int j = blockIdx.x / 3;
    int hb = blockIdx.x % 3;
    int tid = threadIdx.x;
    int h = hb * 256 + tid;
    kms[tid] = (kmask[j * NS + tid] > 0.f) ? 1.f : 0.f;
    __syncthreads();

    float a = alpha_raw[0];
    float alpha = (a > 20.f) ? a : log1pf(expf(a));
    float r = expf(-alpha);
    float scale = expf(logit_scale[0]);

    const __half* kp = g_Kh + (size_t)j * NS * NH + h;
    __half* kwp = g_Kw + (size_t)j * NS * NH + h;

    float a0[16], a1[16];
    float f = 0.f, ksum = 0.f;

    // forward scan (t ascending), phases of 16, double-buffered loads
    CONV_LOAD(a0, 0);
    #pragma unroll
    for (int pp = 0; pp < 8; ++pp) {
        int p0 = 2 * pp;
        if (p0 + 1 < 16) { CONV_LOAD(a1, (p0 + 1) * 16); }
        #pragma unroll
        for (int u = 0; u < 16; ++u) {
            int t = p0 * 16 + u;
            ksum += a0[u];
            f = a0[u] + r * f;
            fbuf[t * 256 + tid] = __float2half(scale * f);
        }
        if (p0 + 2 < 16) { CONV_LOAD(a0, (p0 + 2) * 16); }
        #pragma unroll
        for (int u = 0; u < 16; ++u) {
            int t = (p0 + 1) * 16 + u;
            ksum += a1[u];
            f = a1[u] + r * f;
            fbuf[t * 256 + tid] = __float2half(scale * f);
        }
    }
    g_KsumH[j * NH + h] = __float2half(ksum);

    // backward scan (t descending): Kw[t] = fbuf[t] + scale * gAfter
    float g = 0.f;
    CONV_LOADR(a0, 255);
    #pragma unroll
    for (int pp = 0; pp < 8; ++pp) {
        int p0 = 2 * pp;
        if (p0 + 1 < 16) { CONV_LOADR(a1, 255 - (p0 + 1) * 16); }
        #pragma unroll
        for (int u = 0; u < 16; ++u) {
            int t = 255 - (p0 * 16 + u);
            float gA = r * g;
            float prev = __half2float(fbuf[t * 256 + tid]);
            kwp[(size_t)t * NH] = __float2half(prev + scale * gA);
            g = a0[u] + gA;
        }
        if (p0 + 2 < 16) { CONV_LOADR(a0, 255 - (p0 + 2) * 16); }
        #pragma unroll
        for (int u = 0; u < 16; ++u) {
            int t = 255 - ((p0 + 1) * 16 + u);
            float gA = r * g;
            float prev = __half2float(fbuf[t * 256 + tid]);
            kwp[(size_t)t * NH] = __float2half(prev + scale * gA);
            g = a1[u] + gA;
        }
    }

    if (hb == 0 && tid == 0) {
        float m = 0.f;
        for (int t = 0; t < NS; ++t) m += kms[t];
        g_Mj[j] = m;
    }
}

// ---------------------------------------------------------------------------
// Swrow (tensor-core, unchanged from R13): one CTA per s, 32x64x768 GEMM.
// ---------------------------------------------------------------------------
__global__ void __launch_bounds__(256, 1)
swrow_kernel() {
    extern __shared__ char sm[];
    uint32_t sb = smem_u32(sm);
    int s = blockIdx.x;
    int tid = threadIdx.x, wid = tid >> 5, lid = tid & 31;

    #pragma unroll
    for (int it = 0; it < 12; ++it) {
        int idx = tid + it * 256;
        int r = idx / 96, g = idx - r * 96;
        cpasync16(sb + SW_A + (uint32_t)(r * AST + g * 16),
                  g_Qh + ((size_t)r * NS + s) * NH + g * 8);
    }
    #pragma unroll
    for (int it = 0; it < 24; ++it) {
        int idx = tid + it * 256;
        int r = idx / 96, g = idx - r * 96;
        const __half* src = (r < 32)
            ? g_Kw + ((size_t)r * NS + s) * NH + g * 8
            : g_KsumH + (size_t)(r - 32) * NH + g * 8;
        cpasync16(sb + SW_B + (uint32_t)(r * AST + g * 16), src);
    }
    CP_COMMIT();
    CP_WAIT0();
    __syncthreads();

    float acc[2][8][4];
    #pragma unroll
    for (int mf = 0; mf < 2; ++mf)
        #pragma unroll
        for (int nf = 0; nf < 8; ++nf)
            #pragma unroll
            for (int u = 0; u < 4; ++u) acc[mf][nf][u] = 0.f;

    uint32_t a_base = sb + SW_A + (lid & 15) * AST + ((lid >> 4) << 4);
    uint32_t b_base = sb + SW_B + (((lid >> 4) & 1) * 8 + (lid & 7)) * AST
                      + (((lid >> 3) & 1) << 4);

    #pragma unroll
    for (int step = 0; step < 6; ++step) {
        uint32_t kb = (uint32_t)(wid * 6 + step) * 32;
        uint32_t A0[4], A1[4];
        ldsm4(A0, a_base + kb);
        ldsm4(A1, a_base + 16 * AST + kb);
        #pragma unroll
        for (int nb = 0; nb < 4; ++nb) {
            uint32_t B[4];
            ldsm4(B, b_base + nb * 16 * AST + kb);
            hmma(acc[0][2 * nb],     A0, B[0], B[1]);
            hmma(acc[0][2 * nb + 1], A0, B[2], B[3]);
            hmma(acc[1][2 * nb],     A1, B[0], B[1]);
            hmma(acc[1][2 * nb + 1], A1, B[2], B[3]);
        }
    }
    __syncthreads();

    float* red = (float*)(sm + SW_RED);     // [8][2048]
    float* mine = red + wid * 2048;
    #pragma unroll
    for (int mf = 0; mf < 2; ++mf)
        #pragma unroll
        for (int nf = 0; nf < 8; ++nf)
            #pragma unroll
            for (int u = 0; u < 4; ++u) {
                int row = mf * 16 + (lid >> 2) + ((u >> 1) << 3);
                int col = nf * 8 + 2 * (lid & 3) + (u & 1);
                mine[row * 64 + col] = acc[mf][nf][u];
            }
    __syncthreads();

    #pragma unroll
    for (int it = 0; it < 8; ++it) {
        int idx = tid + it * 256;
        float v = 0.f;
        #pragma unroll
        for (int w = 0; w < 8; ++w) v += red[w * 2048 + idx];
        int row = idx >> 6, col = idx & 63;
        if (col < 32) g_Sw[((size_t)row * NB + col) * NS + s] = v;
        else          g_Srow[((size_t)row * NB + (col - 32)) * NS + s] = v;
    }
}

// ---------------------------------------------------------------------------
// Band v2: blk = jp*32 + i; CTA handles j0=2jp, j1=2jp+1 (A staged once).
// KC=64, 2 buffers, 1 CTA/SM. 48-wide guarded windows per 16-row group.
// ---------------------------------------------------------------------------
__device__ __forceinline__ void load_chunk2(uint32_t sb, int buf, int c, int tid,
                                            const __half* Qp, const __half* Kp0,
                                            const __half* Kp1) {
    int k0 = c * KC;
    uint32_t bufb = sb + buf * BUF_SZ;
    #pragma unroll
    for (int it = 0; it < 8; ++it) {   // A: 256 rows x 8 groups
        int x = tid + it * 256;
        int r = x >> 3, g = x & 7;
        size_t go = (size_t)r * NH + k0 + g * 8;
        cpasync16(bufb + (uint32_t)(r * ROWB + g * 16), Qp + go);
    }
    #pragma unroll
    for (int it = 0; it < 8; ++it) {   // B j0
        int x = tid + it * 256;
        int r = x >> 3, g = x & 7;
        size_t go = (size_t)r * NH + k0 + g * 8;
        cpasync16(bufb + O_BB + (uint32_t)(r * ROWB + g * 16), Kp0 + go);
    }
    #pragma unroll
    for (int it = 0; it < 8; ++it) {   // B j1
        int x = tid + it * 256;
        int r = x >> 3, g = x & 7;
        size_t go = (size_t)r * NH + k0 + g * 8;
        cpasync16(bufb + O_BB + BJ + (uint32_t)(r * ROWB + g * 16), Kp1 + go);
    }
    CP_COMMIT();
}

__global__ void __launch_bounds__(256, 1)
li_band_kernel(const float* __restrict__ qmask, const float* __restrict__ kmask) {
    extern __shared__ char smem[];
    uint32_t sb = smem_u32(smem);

    int tid = threadIdx.x, wid = tid >> 5, lid = tid & 31;
    int blk = blockIdx.x;
    int jp = blk >> 5;
    int i = blk & 31;
    int j0 = 2 * jp;

    float* ws = (float*)(smem + O_WS);
    float* km = (float*)(smem + O_KM);    // [2][256]
    float* qm = (float*)(smem + O_QM);
    float* red = (float*)(smem + O_RED);  // [2][8]
    ws[tid] = g_w[tid];
    km[tid] = kmask[j0 * NS + tid];
    km[256 + tid] = kmask[(j0 + 1) * NS + tid];
    qm[tid] = qmask[i * NS + tid];

    const __half* Qp = g_Qh + (size_t)i * NS * NH;
    const __half* Kp0 = g_Kh + (size_t)j0 * NS * NH;
    const __half* Kp1 = g_Kh + (size_t)(j0 + 1) * NS * NH;

    float acc[2][2][8][4];
    #pragma unroll
    for (int jj = 0; jj < 2; ++jj)
        #pragma unroll
        for (int mf = 0; mf < 2; ++mf)
            #pragma unroll
            for (int nf = 0; nf < 8; ++nf)
                #pragma unroll
                for (int u = 0; u < 4; ++u) acc[jj][mf][nf][u] = 0.f;

    int m_base = wid * 32;
    int wb = m_base - 16;
    if (wb < 0) wb = 0;
    if (wb > 192) wb = 192;
    int lo0 = (wid == 7) ? 1 : 0;
    int lo1 = (wid == 0) ? 0 : 1;

    uint32_t a_off = (uint32_t)((m_base + (lid & 15)) * ROWB + ((lid >> 4) << 4));
    uint32_t b_row = ((lid >> 4) & 1) * 8 + (lid & 7);
    uint32_t b_off = (uint32_t)((wb + b_row) * ROWB + ((lid >> 3) & 1) * 16);

    load_chunk2(sb, 0, 0, tid, Qp, Kp0, Kp1);

    for (int c = 0; c < NCHUNK; ++c) {
        CP_WAIT0();
        __syncthreads();
        if (c + 1 < NCHUNK)
            load_chunk2(sb, (c + 1) & 1, c + 1, tid, Qp, Kp0, Kp1);

        uint32_t base = sb + (c & 1) * BUF_SZ;
        #pragma unroll
        for (int ks = 0; ks < 4; ++ks) {
            uint32_t kb = ks * 32;
            uint32_t A0f[4], A1f[4], Bf[2][4];
            ldsm4(A0f, base + a_off + kb);
            ldsm4(A1f, base + a_off + 16 * ROWB + kb);
            ldsm4(Bf[0], base + O_BB + b_off + kb);
            #pragma unroll
            for (int u = 0; u < 8; ++u) {
                int jj = u >> 2, nb = u & 3;
                int cur = u & 1;
                if (u < 7) {
                    int u1 = u + 1, jj1 = u1 >> 2, nb1 = u1 & 3;
                    ldsm4(Bf[cur ^ 1],
                          base + O_BB + jj1 * BJ + b_off + nb1 * 16 * ROWB + kb);
                }
                if (nb >= lo0 && nb <= lo0 + 2) {
                    hmma(acc[jj][0][2 * nb],     A0f, Bf[cur][0], Bf[cur][1]);
                    hmma(acc[jj][0][2 * nb + 1], A0f, Bf[cur][2], Bf[cur][3]);
                }
                if (nb >= lo1 && nb <= lo1 + 2) {
                    hmma(acc[jj][1][2 * nb],     A1f, Bf[cur][0], Bf[cur][1]);
                    hmma(acc[jj][1][2 * nb + 1], A1f, Bf[cur][2], Bf[cur][3]);
                }
            }
        }
    }
    __syncthreads();

    // ---- epilogue per j ----
    float shift = ws[0];
    float E = expf(-shift);
    int cb = 2 * (lid & 3);
    int rloc = lid >> 2;

    #pragma unroll
    for (int jj = 0; jj < 2; ++jj) {
        int j = j0 + jj;
        float Mjv = g_Mj[j];
        const float* SwP = g_Sw + ((size_t)i * NB + j) * NS;
        const float* SrP = g_Srow + ((size_t)i * NB + j) * NS;
        const float* kmj = km + jj * 256;

        float warp_score = 0.f;
        #pragma unroll
        for (int mf = 0; mf < 2; ++mf) {
            int lo = mf ? lo1 : lo0;
            #pragma unroll
            for (int half = 0; half < 2; ++half) {
                int s = m_base + mf * 16 + rloc + half * 8;
                float cse = 0.f, csec = 0.f;
                #pragma unroll
                for (int nf = 0; nf < 8; ++nf) {
                    if (nf >= 2 * lo && nf < 2 * lo + 6) {
                        #pragma unroll
                        for (int cc = 0; cc < 2; ++cc) {
                            int t = wb + nf * 8 + cb + cc;
                            if (kmj[t] > 0.f) {
                                float sim = acc[jj][mf][nf][half * 2 + cc];
                                int d = s - t; d = d < 0 ? -d : d;
                                float l = sim * ws[d];
                                float e = __expf(l - shift);
                                cse += e - E * (1.f + l);
                                csec = fmaf(e - E, sim, csec);
                            }
                        }
                    }
                }
                cse  += __shfl_xor_sync(0xffffffffu, cse, 1);
                cse  += __shfl_xor_sync(0xffffffffu, cse, 2);
                csec += __shfl_xor_sync(0xffffffffu, csec, 1);
                csec += __shfl_xor_sync(0xffffffffu, csec, 2);
                if ((lid & 3) == 0) {
                    float qms = qm[s];
                    float se = E * (Mjv + SwP[s]) + cse;
                    float sec = E * SrP[s] + csec;
                    if (se > 0.f && qms > 0.f) warp_score += (sec / se) * qms;
                }
            }
        }
        #pragma unroll
        for (int o = 16; o; o >>= 1)
            warp_score += __shfl_xor_sync(0xffffffffu, warp_score, o);
        if (lid == 0) red[jj * 8 + wid] = warp_score;
    }
    __syncthreads();
    if (tid < 2) {
        float tot = 0.f;
        #pragma unroll
        for (int w = 0; w < 8; ++w) tot += red[tid * 8 + w];
        g_partial[(j0 + tid) * NB + i] = tot;
    }
}

// ---------------------------------------------------------------------------
__global__ void reduce_kernel(const float* __restrict__ qmask, float* __restrict__ out) {
    int i = blockIdx.x;
    int tid = threadIdx.x;
    float v = qmask[i * NS + tid];
    #pragma unroll
    for (int o = 16; o; o >>= 1) v += __shfl_xor_sync(0xffffffffu, v, o);
    __shared__ float red[8];
    __shared__ float qsum_s;
    if ((tid & 31) == 0) red[tid >> 5] = v;
    __syncthreads();
    if (tid == 0) {
        float t = 0.f;
        #pragma unroll
        for (int w = 0; w < 8; ++w) t += red[w];
        qsum_s = fmaxf(t, 1.f);
    }
    __syncthreads();
    if (tid < NB) {
        int jj = tid;
        out[i * NB + jj] = g_partial[jj * NB + i] / qsum_s;
    }
}

extern "C" void kernel_launch(void* const* d_in, const int* in_sizes, int n_in,
                              void* d_out, int out_size) {
    const float* q           = (const float*)d_in[0];
    const float* k           = (const float*)d_in[1];
    const float* qmask       = (const float*)d_in[2];
    const float* kmask       = (const float*)d_in[3];
    const float* alpha_raw   = (const float*)d_in[4];
    const float* logit_scale = (const float*)d_in[5];
    float* out = (float*)d_out;

    cudaFuncSetAttribute(li_band_kernel, cudaFuncAttributeMaxDynamicSharedMemorySize, SMEM_NEED);
    cudaFuncSetAttribute(swrow_kernel, cudaFuncAttributeMaxDynamicSharedMemorySize, SW_SMEM);
    cudaFuncSetAttribute(conv_kernel, cudaFuncAttributeMaxDynamicSharedMemorySize, CONV_SMEM);

    norm_all_kernel<<<2 * NB * NS / 8, 256>>>(q, k, alpha_raw, logit_scale);
    conv_kernel<<<NB * 3, 256, CONV_SMEM>>>(kmask, alpha_raw, logit_scale);
    swrow_kernel<<<NS, 256, SW_SMEM>>>();
    li_band_kernel<<<NB * NB / 2, 256, SMEM_NEED>>>(qmask, kmask);
    reduce_kernel<<<NB, 256>>>(qmask, out);
}